// round 2
// baseline (speedup 1.0000x reference)
#include <cuda_runtime.h>
#include <cstdint>

#define TOKENS   8192
#define DMODEL   1024
#define DFF      4096
#define RANK     128
#define MT       64      // tokens per CTA
#define FC       128     // f-chunk
#define STR      132     // padded smem stride (conflict-free fragment access)

__device__ __forceinline__ uint32_t f2tf(float f) {
    uint32_t u;
    asm("cvt.rna.tf32.f32 %0, %1;" : "=r"(u) : "f"(f));
    return u;
}

__device__ __forceinline__ void mma8(float* c,
                                     uint32_t a0, uint32_t a1, uint32_t a2, uint32_t a3,
                                     uint32_t b0, uint32_t b1) {
    asm volatile(
        "mma.sync.aligned.m16n8k8.row.col.f32.tf32.tf32.f32 "
        "{%0,%1,%2,%3}, {%4,%5,%6,%7}, {%8,%9}, {%0,%1,%2,%3};\n"
        : "+f"(c[0]), "+f"(c[1]), "+f"(c[2]), "+f"(c[3])
        : "r"(a0), "r"(a1), "r"(a2), "r"(a3), "r"(b0), "r"(b1));
}

__global__ void __launch_bounds__(256, 1)
fused_lowrank_mlp_kernel(
    const float* __restrict__ x,
    const float* __restrict__ cfc_U,
    const float* __restrict__ cfc_S,
    const float* __restrict__ cfc_V,
    const float* __restrict__ cfc_b,
    const float* __restrict__ cp_U,
    const float* __restrict__ cp_S,
    const float* __restrict__ cp_V,
    const float* __restrict__ cp_b,
    float* __restrict__ out)
{
    extern __shared__ uint32_t sm[];
    uint32_t* t1s = sm;                        // 64 x STR (tf32 bits)
    uint32_t* hs  = t1s + MT * STR;            // 64 x STR
    uint32_t* vsm = hs + MT * STR;             // 128 x STR
    uint32_t* u2s = vsm + FC * STR;            // 128 x STR
    float* biass  = (float*)(u2s + FC * STR);  // 128
    float* sS     = biass + 128;               // 128
    float* sS2    = sS + 128;                  // 128

    const int tid  = threadIdx.x;
    const int lane = tid & 31;
    const int warp = tid >> 5;
    const int wm   = (warp & 3) * 16;   // warp m-offset (4 warps cover 64 rows)
    const int wn   = (warp >> 2) * 64;  // warp n-offset (2 warps cover 128 cols)
    const int qr   = lane >> 2;         // 0..7
    const int qc   = lane & 3;          // 0..3
    const int m0   = blockIdx.x * MT;

    if (tid < RANK) { sS[tid] = cfc_S[tid]; sS2[tid] = cp_S[tid]; }

    // ---------------- Phase 1: t1 = (X @ U) * S ----------------
    float acc[8][4];
    #pragma unroll
    for (int i = 0; i < 8; i++) {
        #pragma unroll
        for (int j = 0; j < 4; j++) acc[i][j] = 0.f;
    }

    for (int kc = 0; kc < DMODEL; kc += 64) {
        // stage X chunk [64 x 64] into hs (as tf32)
        for (int i = tid; i < 64 * 16; i += 256) {
            int r = i >> 4, s = (i & 15) << 2;
            float4 v = *(const float4*)(x + (size_t)(m0 + r) * DMODEL + kc + s);
            *(uint4*)(hs + r * STR + s) =
                make_uint4(f2tf(v.x), f2tf(v.y), f2tf(v.z), f2tf(v.w));
        }
        // stage U chunk [64 x 128] into vsm
        for (int i = tid; i < 64 * 32; i += 256) {
            int r = i >> 5, s = (i & 31) << 2;
            float4 v = *(const float4*)(cfc_U + (size_t)(kc + r) * RANK + s);
            *(uint4*)(vsm + r * STR + s) =
                make_uint4(f2tf(v.x), f2tf(v.y), f2tf(v.z), f2tf(v.w));
        }
        __syncthreads();
        #pragma unroll 4
        for (int ks = 0; ks < 8; ks++) {
            int k0 = ks * 8;
            uint32_t a0 = hs[(wm + qr) * STR + k0 + qc];
            uint32_t a1 = hs[(wm + qr + 8) * STR + k0 + qc];
            uint32_t a2 = hs[(wm + qr) * STR + k0 + qc + 4];
            uint32_t a3 = hs[(wm + qr + 8) * STR + k0 + qc + 4];
            #pragma unroll
            for (int nt = 0; nt < 8; nt++) {
                int n0 = wn + nt * 8;
                uint32_t b0 = vsm[(k0 + qc) * STR + n0 + qr];
                uint32_t b1 = vsm[(k0 + qc + 4) * STR + n0 + qr];
                mma8(acc[nt], a0, a1, a2, a3, b0, b1);
            }
        }
        __syncthreads();
    }

    // scale columns by S, store tf32 t1 to smem
    #pragma unroll
    for (int nt = 0; nt < 8; nt++) {
        int c0 = wn + nt * 8 + 2 * qc;
        float s0 = sS[c0], s1 = sS[c0 + 1];
        t1s[(wm + qr) * STR + c0]         = f2tf(acc[nt][0] * s0);
        t1s[(wm + qr) * STR + c0 + 1]     = f2tf(acc[nt][1] * s1);
        t1s[(wm + qr + 8) * STR + c0]     = f2tf(acc[nt][2] * s0);
        t1s[(wm + qr + 8) * STR + c0 + 1] = f2tf(acc[nt][3] * s1);
    }
    __syncthreads();

    // ---------------- Phase 2: loop over f-chunks ----------------
    float t2[8][4];
    #pragma unroll
    for (int i = 0; i < 8; i++) {
        #pragma unroll
        for (int j = 0; j < 4; j++) t2[i][j] = 0.f;
    }

    for (int it = 0; it < DFF / FC; it++) {
        const int f0 = it * FC;
        // stage V chunk [128 x 128] -> vsm[j][k], U2 chunk -> u2s[k][n]
        for (int i = tid; i < FC * 32; i += 256) {
            int r = i >> 5, s = (i & 31) << 2;
            float4 v = *(const float4*)(cfc_V + (size_t)(f0 + r) * RANK + s);
            *(uint4*)(vsm + r * STR + s) =
                make_uint4(f2tf(v.x), f2tf(v.y), f2tf(v.z), f2tf(v.w));
            float4 u = *(const float4*)(cp_U + (size_t)(f0 + r) * RANK + s);
            *(uint4*)(u2s + r * STR + s) =
                make_uint4(f2tf(u.x), f2tf(u.y), f2tf(u.z), f2tf(u.w));
        }
        if (tid < FC) biass[tid] = cfc_b[f0 + tid];
        __syncthreads();

        // GEMM2: h = t1 @ V_chunk^T   (K = RANK = 128)
        float hacc[8][4];
        #pragma unroll
        for (int i = 0; i < 8; i++) {
            #pragma unroll
            for (int j = 0; j < 4; j++) hacc[i][j] = 0.f;
        }
        #pragma unroll 4
        for (int ks = 0; ks < RANK / 8; ks++) {
            int k0 = ks * 8;
            uint32_t a0 = t1s[(wm + qr) * STR + k0 + qc];
            uint32_t a1 = t1s[(wm + qr + 8) * STR + k0 + qc];
            uint32_t a2 = t1s[(wm + qr) * STR + k0 + qc + 4];
            uint32_t a3 = t1s[(wm + qr + 8) * STR + k0 + qc + 4];
            #pragma unroll
            for (int nt = 0; nt < 8; nt++) {
                int n0 = wn + nt * 8;
                uint32_t b0 = vsm[(n0 + qr) * STR + k0 + qc];
                uint32_t b1 = vsm[(n0 + qr) * STR + k0 + qc + 4];
                mma8(hacc[nt], a0, a1, a2, a3, b0, b1);
            }
        }

        // bias + exact GELU, store tf32 h to smem
        #pragma unroll
        for (int nt = 0; nt < 8; nt++) {
            int c0 = wn + nt * 8 + 2 * qc;
            float b0f = biass[c0], b1f = biass[c0 + 1];
            float v00 = hacc[nt][0] + b0f;
            float v01 = hacc[nt][1] + b1f;
            float v10 = hacc[nt][2] + b0f;
            float v11 = hacc[nt][3] + b1f;
            v00 = 0.5f * v00 * (1.f + erff(v00 * 0.7071067811865476f));
            v01 = 0.5f * v01 * (1.f + erff(v01 * 0.7071067811865476f));
            v10 = 0.5f * v10 * (1.f + erff(v10 * 0.7071067811865476f));
            v11 = 0.5f * v11 * (1.f + erff(v11 * 0.7071067811865476f));
            hs[(wm + qr) * STR + c0]         = f2tf(v00);
            hs[(wm + qr) * STR + c0 + 1]     = f2tf(v01);
            hs[(wm + qr + 8) * STR + c0]     = f2tf(v10);
            hs[(wm + qr + 8) * STR + c0 + 1] = f2tf(v11);
        }
        __syncthreads();

        // GEMM3: t2 += h @ U2_chunk   (K = FC = 128)
        #pragma unroll 4
        for (int ks = 0; ks < FC / 8; ks++) {
            int k0 = ks * 8;
            uint32_t a0 = hs[(wm + qr) * STR + k0 + qc];
            uint32_t a1 = hs[(wm + qr + 8) * STR + k0 + qc];
            uint32_t a2 = hs[(wm + qr) * STR + k0 + qc + 4];
            uint32_t a3 = hs[(wm + qr + 8) * STR + k0 + qc + 4];
            #pragma unroll
            for (int nt = 0; nt < 8; nt++) {
                int n0 = wn + nt * 8;
                uint32_t b0 = u2s[(k0 + qc) * STR + n0 + qr];
                uint32_t b1 = u2s[(k0 + qc + 4) * STR + n0 + qr];
                mma8(t2[nt], a0, a1, a2, a3, b0, b1);
            }
        }
        __syncthreads();   // protect vsm/u2s before next stage
    }

    // scale t2 by S2, store tf32 into t1s (reuse)
    #pragma unroll
    for (int nt = 0; nt < 8; nt++) {
        int c0 = wn + nt * 8 + 2 * qc;
        float s0 = sS2[c0], s1 = sS2[c0 + 1];
        t1s[(wm + qr) * STR + c0]         = f2tf(t2[nt][0] * s0);
        t1s[(wm + qr) * STR + c0 + 1]     = f2tf(t2[nt][1] * s1);
        t1s[(wm + qr + 8) * STR + c0]     = f2tf(t2[nt][2] * s0);
        t1s[(wm + qr + 8) * STR + c0 + 1] = f2tf(t2[nt][3] * s1);
    }
    __syncthreads();

    // ---------------- Phase 3: out = t2 @ V2^T + b2 ----------------
    for (int dc = 0; dc < DMODEL / FC; dc++) {
        const int d0 = dc * FC;
        for (int i = tid; i < FC * 32; i += 256) {
            int r = i >> 5, s = (i & 31) << 2;
            float4 v = *(const float4*)(cp_V + (size_t)(d0 + r) * RANK + s);
            *(uint4*)(vsm + r * STR + s) =
                make_uint4(f2tf(v.x), f2tf(v.y), f2tf(v.z), f2tf(v.w));
        }
        if (tid < FC) biass[tid] = cp_b[d0 + tid];
        __syncthreads();

        float oacc[8][4];
        #pragma unroll
        for (int i = 0; i < 8; i++) {
            #pragma unroll
            for (int j = 0; j < 4; j++) oacc[i][j] = 0.f;
        }
        #pragma unroll 4
        for (int ks = 0; ks < RANK / 8; ks++) {
            int k0 = ks * 8;
            uint32_t a0 = t1s[(wm + qr) * STR + k0 + qc];
            uint32_t a1 = t1s[(wm + qr + 8) * STR + k0 + qc];
            uint32_t a2 = t1s[(wm + qr) * STR + k0 + qc + 4];
            uint32_t a3 = t1s[(wm + qr + 8) * STR + k0 + qc + 4];
            #pragma unroll
            for (int nt = 0; nt < 8; nt++) {
                int n0 = wn + nt * 8;
                uint32_t b0 = vsm[(n0 + qr) * STR + k0 + qc];
                uint32_t b1 = vsm[(n0 + qr) * STR + k0 + qc + 4];
                mma8(oacc[nt], a0, a1, a2, a3, b0, b1);
            }
        }

        #pragma unroll
        for (int nt = 0; nt < 8; nt++) {
            int cc = wn + nt * 8 + 2 * qc;
            float b0f = biass[cc], b1f = biass[cc + 1];
            size_t rowoff = (size_t)(m0 + wm + qr) * DMODEL + d0 + cc;
            *(float2*)(out + rowoff) =
                make_float2(oacc[nt][0] + b0f, oacc[nt][1] + b1f);
            *(float2*)(out + rowoff + (size_t)8 * DMODEL) =
                make_float2(oacc[nt][2] + b0f, oacc[nt][3] + b1f);
        }
        __syncthreads();
    }
}

extern "C" void kernel_launch(void* const* d_in, const int* in_sizes, int n_in,
                              void* d_out, int out_size)
{
    const float* x     = (const float*)d_in[0];
    const float* cfc_U = (const float*)d_in[1];
    const float* cfc_S = (const float*)d_in[2];
    const float* cfc_V = (const float*)d_in[3];
    const float* cfc_b = (const float*)d_in[4];
    const float* cp_U  = (const float*)d_in[5];
    const float* cp_S  = (const float*)d_in[6];
    const float* cp_V  = (const float*)d_in[7];
    const float* cp_b  = (const float*)d_in[8];
    float* out = (float*)d_out;

    const int smem_bytes = (2 * MT * STR + 2 * FC * STR + 3 * 128) * 4;  // 204288
    cudaFuncSetAttribute(fused_lowrank_mlp_kernel,
                         cudaFuncAttributeMaxDynamicSharedMemorySize, smem_bytes);

    fused_lowrank_mlp_kernel<<<TOKENS / MT, 256, smem_bytes>>>(
        x, cfc_U, cfc_S, cfc_V, cfc_b, cp_U, cp_S, cp_V, cp_b, out);
}